// round 12
// baseline (speedup 1.0000x reference)
#include <cuda_runtime.h>
#include <cuda_bf16.h>
#include <cuda_fp16.h>
#include <math.h>
#include <stdint.h>

#define Nn   50000
#define Ee   1000000
#define Hh   4
#define Dd   64
#define NH   (Nn * Hh)   // 200000
#define HD   (Hh * Dd)   // 256
#define KA   512         // A storage: [Ah | Al]
#define KK   768         // B storage: [Bh | Bl | Bh]; virtual GEMM K
#define SMEM_GEMM (3 * 32768)

// ---------------- scratch (device globals; no allocation allowed) ----------
__device__ __half g_hf[Nn * HD];    // fp16 node features for the gather pass
__device__ float  g_ssrc[NH];
__device__ float  g_sdst[NH];
// CSR (dst-bucketed) edge structures
__device__ int    g_cnt[Nn];
__device__ int    g_off[Nn];
__device__ int    g_cur[Nn];
__device__ int    g_srcs[Ee];
__device__ int    g_total;          // global offset counter
// packed split-bf16 operands
__device__ __nv_bfloat16 g_a2[Nn * KA];    // [xh | xl]
__device__ __nv_bfloat16 g_o2[Nn * KA];    // normalized out_h packed [hi | lo]
__device__ __nv_bfloat16 g_b1[256 * KK];   // W  head-blocked, row n = out col
__device__ __nv_bfloat16 g_b2[256 * KK];   // W_out transposed

#define SWZ(o) ((o) ^ (((o) >> 3) & 0x70))

__device__ __forceinline__ uint32_t smem_u32(const void* p) {
    uint32_t a;
    asm("{ .reg .u64 t; cvta.to.shared.u64 t, %1; cvt.u32.u64 %0, t; }"
        : "=r"(a) : "l"(p));
    return a;
}
__device__ __forceinline__ void cp16(uint32_t dst, const void* src) {
    asm volatile("cp.async.cg.shared.global [%0], [%1], 16;"
                 :: "r"(dst), "l"(src) : "memory");
}
__device__ __forceinline__ void ldm_x4(uint32_t* r, uint32_t addr) {
    asm volatile("ldmatrix.sync.aligned.m8n8.x4.shared.b16 {%0,%1,%2,%3}, [%4];"
                 : "=r"(r[0]), "=r"(r[1]), "=r"(r[2]), "=r"(r[3]) : "r"(addr));
}
__device__ __forceinline__ void mma16816(float* c, const uint32_t* a,
                                         uint32_t b0, uint32_t b1) {
    asm volatile(
        "mma.sync.aligned.m16n8k16.row.col.f32.bf16.bf16.f32 "
        "{%0,%1,%2,%3}, {%4,%5,%6,%7}, {%8,%9}, {%0,%1,%2,%3};"
        : "+f"(c[0]), "+f"(c[1]), "+f"(c[2]), "+f"(c[3])
        : "r"(a[0]), "r"(a[1]), "r"(a[2]), "r"(a[3]), "r"(b0), "r"(b1));
}

// ---------------- init + CSR build ------------------------------------------
__global__ void k_init0() {
    int i = blockIdx.x * blockDim.x + threadIdx.x;
    if (i == 0) g_total = 0;
    if (i < Nn) g_cnt[i] = 0;
    if (i < NH) { g_ssrc[i] = 0.f; g_sdst[i] = 0.f; }
}
__global__ void k_hist(const int* __restrict__ ei) {
    int e = blockIdx.x * blockDim.x + threadIdx.x;
    if (e < Ee) atomicAdd(&g_cnt[ei[Ee + e]], 1);
}
// parallel offsets: warp-scan + one global atomic per warp. Offsets are
// disjoint ranges (order across warps is arbitrary — CSR doesn't care).
__global__ void k_offs() {
    int i = blockIdx.x * blockDim.x + threadIdx.x;
    int lane = threadIdx.x & 31;
    int c = (i < Nn) ? g_cnt[i] : 0;
    int incl = c;
#pragma unroll
    for (int o = 1; o < 32; o <<= 1) {
        int v = __shfl_up_sync(0xFFFFFFFFu, incl, o);
        if (lane >= o) incl += v;
    }
    int total = __shfl_sync(0xFFFFFFFFu, incl, 31);
    int base = 0;
    if (lane == 31) base = atomicAdd(&g_total, total);
    base = __shfl_sync(0xFFFFFFFFu, base, 31);
    int off = base + incl - c;
    if (i < Nn) { g_off[i] = off; g_cur[i] = off; }
}

// ---------------- edge pass: pure permutation build --------------------------
__global__ void k_edge_sort(const int* __restrict__ ei) {
    int t = blockIdx.x * blockDim.x + threadIdx.x;
    int e0 = t * 4;
    if (e0 >= Ee) return;
    int4 sv = *(const int4*)(ei + e0);
    int4 dv = *(const int4*)(ei + Ee + e0);
    int ss4[4] = { sv.x, sv.y, sv.z, sv.w };
    int dd4[4] = { dv.x, dv.y, dv.z, dv.w };
#pragma unroll
    for (int i = 0; i < 4; i++) {
        int pos = atomicAdd(&g_cur[dd4[i]], 1);
        g_srcs[pos] = ss4[i];
    }
}

// ---------------- pack fp32 -> [hi | lo] bf16 -------------------------------
__device__ __forceinline__ void pack_split(const float* f, uint2& ph, uint2& pl) {
    unsigned short hs[4], ls[4];
#pragma unroll
    for (int i = 0; i < 4; i++) {
        __nv_bfloat16 h = __float2bfloat16(f[i]);
        __nv_bfloat16 l = __float2bfloat16(f[i] - __bfloat162float(h));
        hs[i] = __bfloat16_as_ushort(h);
        ls[i] = __bfloat16_as_ushort(l);
    }
    ph = make_uint2((uint32_t)hs[0] | ((uint32_t)hs[1] << 16),
                    (uint32_t)hs[2] | ((uint32_t)hs[3] << 16));
    pl = make_uint2((uint32_t)ls[0] | ((uint32_t)ls[1] << 16),
                    (uint32_t)ls[2] | ((uint32_t)ls[3] << 16));
}

// ---------------- merged prep: weights (blocks 0..255) + x (rest) -----------
__global__ void k_prep(const float* __restrict__ W, const float* __restrict__ Wout,
                       const float* __restrict__ x) {
    if (blockIdx.x < 256) {
        int t = blockIdx.x * 256 + threadIdx.x;   // 65536
        int n = t >> 8, k = t & 255;
        float v1 = W[(((n >> 6) * 256) + k) * 64 + (n & 63)];
        __nv_bfloat16 h1 = __float2bfloat16(v1);
        __nv_bfloat16 l1 = __float2bfloat16(v1 - __bfloat162float(h1));
        g_b1[n * KK + k]       = h1;
        g_b1[n * KK + 256 + k] = l1;
        g_b1[n * KK + 512 + k] = h1;
        float v2 = Wout[k * 256 + n];
        __nv_bfloat16 h2 = __float2bfloat16(v2);
        __nv_bfloat16 l2 = __float2bfloat16(v2 - __bfloat162float(h2));
        g_b2[n * KK + k]       = h2;
        g_b2[n * KK + 256 + k] = l2;
        g_b2[n * KK + 512 + k] = h2;
    } else {
        int t = (blockIdx.x - 256) * 256 + threadIdx.x;   // per float4
        if (t >= Nn * 64) return;
        float4 v = ((const float4*)x)[t];
        float f[4] = { v.x, v.y, v.z, v.w };
        uint2 ph, pl;
        pack_split(f, ph, pl);
        long base = (long)(t >> 6) * KA + (t & 63) * 4;
        *(uint2*)(g_a2 + base)       = ph;
        *(uint2*)(g_a2 + base + 256) = pl;
    }
}

// ---------------- bf16 mma.sync GEMM (3-stage cp.async pipeline) -------------
// C[M,256] = A[M,512:(hi|lo)] x B[256,768:(Bh|Bl|Bh)]^T over virtual K=768.
// C may be nullptr; Chalf optional fp16 copy; attnp != nullptr fuses the
// attention-score reduction into the epilogue.
__global__ void __launch_bounds__(256, 2) k_gemm_mma(
    const __nv_bfloat16* __restrict__ A, const __nv_bfloat16* __restrict__ B,
    float* __restrict__ C, __half* __restrict__ Chalf,
    const float* __restrict__ attnp, int M)
{
    extern __shared__ char sm[];
    uint32_t sbase = smem_u32(sm);
    const int tid = threadIdx.x;
    const int wid = tid >> 5, lid = tid & 31;
    const int bm = blockIdx.y * 128, bn = blockIdx.x * 128;
    const int wm = (wid >> 2) * 64, wn = (wid & 3) * 32;

    const int arow = (lid & 7) + ((lid >> 3) & 1) * 8;
    const int acol = (lid >> 4) * 8;
    const int q = lid >> 3;
    const int brow = (lid & 7) + (q >> 1) * 8;
    const int bcol = (q & 1) * 8;

    float acc[4][4][4];
#pragma unroll
    for (int mi = 0; mi < 4; mi++)
#pragma unroll
        for (int ni = 0; ni < 4; ni++)
#pragma unroll
            for (int j = 0; j < 4; j++) acc[mi][ni][j] = 0.f;

    auto load_chunk = [&](int c, int s) {
        uint32_t abase = sbase + s * 32768;
        int aoff = (c & 3) * 64 + ((c >= 8) ? 256 : 0);
#pragma unroll
        for (int it = 0; it < 4; it++) {
            int idx = tid + it * 256;
            int row = idx >> 3, col = (idx & 7) * 8;
            long ar = bm + row; if (ar >= M) ar = M - 1;
            cp16(abase + SWZ(row * 128 + col * 2), A + ar * KA + aoff + col);
        }
#pragma unroll
        for (int it = 0; it < 4; it++) {
            int idx = tid + it * 256;
            int row = idx >> 3, col = (idx & 7) * 8;
            cp16(abase + 16384 + SWZ(row * 128 + col * 2),
                 B + (long)(bn + row) * KK + c * 64 + col);
        }
        asm volatile("cp.async.commit_group;" ::: "memory");
    };

    auto compute_chunk = [&](int s) {
        uint32_t abase = sbase + s * 32768;
        uint32_t bbase = abase + 16384;
#pragma unroll
        for (int ks = 0; ks < 4; ks++) {
            uint32_t a[4][4];
#pragma unroll
            for (int mi = 0; mi < 4; mi++)
                ldm_x4(a[mi], abase + SWZ((wm + mi * 16 + arow) * 128 +
                                          (ks * 16 + acol) * 2));
            uint32_t b[2][4];
#pragma unroll
            for (int nj = 0; nj < 2; nj++)
                ldm_x4(b[nj], bbase + SWZ((wn + nj * 16 + brow) * 128 +
                                          (ks * 16 + bcol) * 2));
#pragma unroll
            for (int mi = 0; mi < 4; mi++)
#pragma unroll
                for (int ni = 0; ni < 4; ni++)
                    mma16816(acc[mi][ni], a[mi],
                             b[ni >> 1][(ni & 1) * 2], b[ni >> 1][(ni & 1) * 2 + 1]);
        }
    };

    const int NC = 12;
    load_chunk(0, 0);
    load_chunk(1, 1);
    for (int c = 0; c < NC; c++) {
        if (c + 2 < NC) {
            load_chunk(c + 2, (c + 2) % 3);
            asm volatile("cp.async.wait_group 2;" ::: "memory");
        } else if (c + 1 < NC) {
            asm volatile("cp.async.wait_group 1;" ::: "memory");
        } else {
            asm volatile("cp.async.wait_group 0;" ::: "memory");
        }
        __syncthreads();
        compute_chunk(c % 3);
        __syncthreads();
    }

    const int g = lid >> 2, tig = lid & 3;

#pragma unroll
    for (int mi = 0; mi < 4; mi++) {
        int r0 = bm + wm + mi * 16 + g;
#pragma unroll
        for (int ni = 0; ni < 4; ni++) {
            int col = bn + wn + ni * 8 + tig * 2;
#pragma unroll
            for (int h2 = 0; h2 < 2; h2++) {
                int r = r0 + h2 * 8;
                if (r < M) {
                    float c0 = acc[mi][ni][h2 * 2];
                    float c1 = acc[mi][ni][h2 * 2 + 1];
                    if (C)
                        *(float2*)(C + (long)r * 256 + col) = make_float2(c0, c1);
                    if (Chalf)
                        *(__half2*)(Chalf + (long)r * 256 + col) =
                            __floats2half2_rn(c0, c1);
                }
            }
        }
    }

    // fused attention-score reduction (GEMM1 only)
    if (attnp) {
        int hh = ((bn + wn) >> 6) & 3;
        int dbase = (bn + wn) & 63;
        float as[8], ad[8];
#pragma unroll
        for (int ni = 0; ni < 4; ni++)
#pragma unroll
            for (int c2 = 0; c2 < 2; c2++) {
                int dd = dbase + ni * 8 + tig * 2 + c2;
                as[ni * 2 + c2] = __ldg(attnp + hh * 128 + dd);
                ad[ni * 2 + c2] = __ldg(attnp + hh * 128 + 64 + dd);
            }
#pragma unroll
        for (int mi = 0; mi < 4; mi++)
#pragma unroll
            for (int h2 = 0; h2 < 2; h2++) {
                int r = bm + wm + mi * 16 + g + h2 * 8;
                if (r < M) {
                    float ps = 0.f, pd = 0.f;
#pragma unroll
                    for (int ni = 0; ni < 4; ni++) {
                        float c0 = acc[mi][ni][h2 * 2];
                        float c1 = acc[mi][ni][h2 * 2 + 1];
                        ps += c0 * as[ni * 2] + c1 * as[ni * 2 + 1];
                        pd += c0 * ad[ni * 2] + c1 * ad[ni * 2 + 1];
                    }
                    atomicAdd(&g_ssrc[r * 4 + hh], ps);
                    atomicAdd(&g_sdst[r * 4 + hh], pd);
                }
            }
    }
}

__device__ __forceinline__ float leaky(float v) {
    return v > 0.f ? v : 0.2f * v;
}

// ---------------- gather aggregation + alpha + normalize + pack -------------
__global__ void __launch_bounds__(64) k_agg() {
    __shared__ int   s_src[64];
    __shared__ float s_alp[64][4];
    int d = blockIdx.x;
    int j = threadIdx.x;             // 0..63 : float4 group within 256-row
    int h = j >> 4;
    int beg = g_off[d], cnt = g_cnt[d];
    float4 sd4 = *(const float4*)(g_sdst + d * 4);
    float4 acc = make_float4(0.f, 0.f, 0.f, 0.f);
    float asum = 0.f;
    for (int base = 0; base < cnt; base += 64) {
        int nb = min(64, cnt - base);
        if (j < nb) {
            int k = beg + base + j;
            int s = g_srcs[k];
            s_src[j] = s;
            float4 sv = *(const float4*)(g_ssrc + s * 4);
            s_alp[j][0] = __expf(leaky(sv.x + sd4.x));
            s_alp[j][1] = __expf(leaky(sv.y + sd4.y));
            s_alp[j][2] = __expf(leaky(sv.z + sd4.z));
            s_alp[j][3] = __expf(leaky(sv.w + sd4.w));
        }
        __syncthreads();
#pragma unroll 4
        for (int t = 0; t < nb; t++) {
            int s = s_src[t];
            float a = s_alp[t][h];
            const __half2* hp = (const __half2*)(g_hf + (long)s * HD + j * 4);
            float2 f0 = __half22float2(hp[0]);
            float2 f1 = __half22float2(hp[1]);
            asum += a;
            acc.x = fmaf(a, f0.x, acc.x);
            acc.y = fmaf(a, f0.y, acc.y);
            acc.z = fmaf(a, f1.x, acc.z);
            acc.w = fmaf(a, f1.y, acc.w);
        }
        __syncthreads();
    }
    float inv = 1.f / (asum + 1e-8f);
    float f[4] = { acc.x * inv, acc.y * inv, acc.z * inv, acc.w * inv };
    uint2 ph, pl;
    pack_split(f, ph, pl);
    long base2 = (long)d * KA + j * 4;
    *(uint2*)(g_o2 + base2)       = ph;
    *(uint2*)(g_o2 + base2 + 256) = pl;
}

// ---------------- launch ----------------------------------------------------
extern "C" void kernel_launch(void* const* d_in, const int* in_sizes, int n_in,
                              void* d_out, int out_size)
{
    const float* x    = (const float*)d_in[0];
    const int*   ei   = (const int*)  d_in[1];
    const float* W    = (const float*)d_in[2];
    const float* attn = (const float*)d_in[3];
    const float* Wout = (const float*)d_in[4];
    float*       out  = (float*)d_out;

    void *p_hf, *p_a2, *p_o2, *p_b1, *p_b2;
    cudaGetSymbolAddress(&p_hf, g_hf);
    cudaGetSymbolAddress(&p_a2, g_a2);
    cudaGetSymbolAddress(&p_o2, g_o2);
    cudaGetSymbolAddress(&p_b1, g_b1);
    cudaGetSymbolAddress(&p_b2, g_b2);

    cudaFuncSetAttribute(k_gemm_mma, cudaFuncAttributeMaxDynamicSharedMemorySize,
                         SMEM_GEMM);

    // side stream for init + CSR build (capture-safe fork/join).
    cudaStream_t s1;
    cudaStreamCreateWithFlags(&s1, cudaStreamNonBlocking);
    cudaEvent_t e0, eInit, e1;
    cudaEventCreateWithFlags(&e0, cudaEventDisableTiming);
    cudaEventCreateWithFlags(&eInit, cudaEventDisableTiming);
    cudaEventCreateWithFlags(&e1, cudaEventDisableTiming);

    int eb = (Ee + 255) / 256;

    // fork immediately: s1 runs init (zeroes cnt + scores) then CSR build
    cudaEventRecord(e0, 0);
    cudaStreamWaitEvent(s1, e0, 0);
    k_init0<<<(NH + 255) / 256, 256, 0, s1>>>();
    cudaEventRecord(eInit, s1);
    k_hist<<<eb, 256, 0, s1>>>(ei);
    k_offs<<<(Nn + 255) / 256, 256, 0, s1>>>();
    k_edge_sort<<<(Ee / 4 + 255) / 256, 256, 0, s1>>>(ei);
    cudaEventRecord(e1, s1);

    // main stream: prep starts immediately (independent of init/CSR)
    k_prep<<<256 + (Nn * 64 + 255) / 256, 256>>>(W, Wout, x);

    // GEMM1's score epilogue needs g_ssrc/g_sdst zeroed
    cudaStreamWaitEvent(0, eInit, 0);

    dim3 gg(2, (Nn + 127) / 128);           // n-tiles fast -> A shared via L2
    k_gemm_mma<<<gg, 256, SMEM_GEMM>>>((const __nv_bfloat16*)p_a2,
                                       (const __nv_bfloat16*)p_b1,
                                       (float*)nullptr, (__half*)p_hf, attn, Nn);

    // join: agg needs both GEMM1 results and the CSR permutation
    cudaStreamWaitEvent(0, e1, 0);

    k_agg<<<Nn, 64>>>();

    k_gemm_mma<<<gg, 256, SMEM_GEMM>>>((const __nv_bfloat16*)p_o2,
                                       (const __nv_bfloat16*)p_b2,
                                       out, (__half*)nullptr,
                                       (const float*)nullptr, Nn);
}

// round 13
// speedup vs baseline: 1.2691x; 1.2691x over previous
#include <cuda_runtime.h>
#include <cuda_bf16.h>
#include <cuda_fp16.h>
#include <math.h>
#include <stdint.h>

#define Nn   50000
#define Ee   1000000
#define Hh   4
#define Dd   64
#define NH   (Nn * Hh)   // 200000
#define HD   (Hh * Dd)   // 256
#define KB2  512         // B storage: [Bh | Bl] fp16; virtual GEMM K = 512

// ---------------- scratch (device globals; no allocation allowed) ----------
__device__ __half g_hf[Nn * HD];    // fp16 node features (GEMM1 out, gather in)
__device__ float  g_ssrc[NH];
__device__ float  g_sdst[NH];
// CSR (dst-bucketed) edge structures
__device__ int    g_cnt[Nn];
__device__ int    g_off[Nn];
__device__ int    g_cur[Nn];
__device__ int    g_srcs[Ee];
__device__ int    g_total;          // global offset counter
// fp16 GEMM operands
__device__ __half g_a2[Nn * HD];    // x in fp16 (GEMM1 A)
__device__ __half g_o2[Nn * HD];    // normalized out_h in fp16 (GEMM2 A)
__device__ __half g_b1[256 * KB2];  // W  head-blocked [n][Bh|Bl], row n = out col
__device__ __half g_b2[256 * KB2];  // W_out transposed [n][Bh|Bl]

#define SWZ(o) ((o) ^ (((o) >> 3) & 0x70))

__device__ __forceinline__ uint32_t smem_u32(const void* p) {
    uint32_t a;
    asm("{ .reg .u64 t; cvta.to.shared.u64 t, %1; cvt.u32.u64 %0, t; }"
        : "=r"(a) : "l"(p));
    return a;
}
__device__ __forceinline__ void cp16(uint32_t dst, const void* src) {
    asm volatile("cp.async.cg.shared.global [%0], [%1], 16;"
                 :: "r"(dst), "l"(src) : "memory");
}
__device__ __forceinline__ void ldm_x4(uint32_t* r, uint32_t addr) {
    asm volatile("ldmatrix.sync.aligned.m8n8.x4.shared.b16 {%0,%1,%2,%3}, [%4];"
                 : "=r"(r[0]), "=r"(r[1]), "=r"(r[2]), "=r"(r[3]) : "r"(addr));
}
__device__ __forceinline__ void mma16816(float* c, const uint32_t* a,
                                         uint32_t b0, uint32_t b1) {
    asm volatile(
        "mma.sync.aligned.m16n8k16.row.col.f32.f16.f16.f32 "
        "{%0,%1,%2,%3}, {%4,%5,%6,%7}, {%8,%9}, {%0,%1,%2,%3};"
        : "+f"(c[0]), "+f"(c[1]), "+f"(c[2]), "+f"(c[3])
        : "r"(a[0]), "r"(a[1]), "r"(a[2]), "r"(a[3]), "r"(b0), "r"(b1));
}

// ---------------- init + CSR build ------------------------------------------
__global__ void k_init0() {
    int i = blockIdx.x * blockDim.x + threadIdx.x;
    if (i == 0) g_total = 0;
    if (i < Nn) g_cnt[i] = 0;
    if (i < NH) { g_ssrc[i] = 0.f; g_sdst[i] = 0.f; }
}
__global__ void k_hist(const int* __restrict__ ei) {
    int e = blockIdx.x * blockDim.x + threadIdx.x;
    if (e < Ee) atomicAdd(&g_cnt[ei[Ee + e]], 1);
}
// parallel offsets: warp-scan + one global atomic per warp.
__global__ void k_offs() {
    int i = blockIdx.x * blockDim.x + threadIdx.x;
    int lane = threadIdx.x & 31;
    int c = (i < Nn) ? g_cnt[i] : 0;
    int incl = c;
#pragma unroll
    for (int o = 1; o < 32; o <<= 1) {
        int v = __shfl_up_sync(0xFFFFFFFFu, incl, o);
        if (lane >= o) incl += v;
    }
    int total = __shfl_sync(0xFFFFFFFFu, incl, 31);
    int base = 0;
    if (lane == 31) base = atomicAdd(&g_total, total);
    base = __shfl_sync(0xFFFFFFFFu, base, 31);
    int off = base + incl - c;
    if (i < Nn) { g_off[i] = off; g_cur[i] = off; }
}

// ---------------- edge pass: pure permutation build --------------------------
__global__ void k_edge_sort(const int* __restrict__ ei) {
    int t = blockIdx.x * blockDim.x + threadIdx.x;
    int e0 = t * 4;
    if (e0 >= Ee) return;
    int4 sv = *(const int4*)(ei + e0);
    int4 dv = *(const int4*)(ei + Ee + e0);
    int ss4[4] = { sv.x, sv.y, sv.z, sv.w };
    int dd4[4] = { dv.x, dv.y, dv.z, dv.w };
#pragma unroll
    for (int i = 0; i < 4; i++) {
        int pos = atomicAdd(&g_cur[dd4[i]], 1);
        g_srcs[pos] = ss4[i];
    }
}

// ---------------- merged prep: weights (blocks 0..255) + x (rest) -----------
__global__ void k_prep(const float* __restrict__ W, const float* __restrict__ Wout,
                       const float* __restrict__ x) {
    if (blockIdx.x < 256) {
        int t = blockIdx.x * 256 + threadIdx.x;   // 65536
        int n = t >> 8, k = t & 255;
        float v1 = W[(((n >> 6) * 256) + k) * 64 + (n & 63)];
        __half h1 = __float2half_rn(v1);
        __half l1 = __float2half_rn(v1 - __half2float(h1));
        g_b1[n * KB2 + k]       = h1;
        g_b1[n * KB2 + 256 + k] = l1;
        float v2 = Wout[k * 256 + n];
        __half h2 = __float2half_rn(v2);
        __half l2 = __float2half_rn(v2 - __half2float(h2));
        g_b2[n * KB2 + k]       = h2;
        g_b2[n * KB2 + 256 + k] = l2;
    } else {
        int t = (blockIdx.x - 256) * 256 + threadIdx.x;   // per float4
        if (t >= Nn * 64) return;
        float4 v = ((const float4*)x)[t];
        __half2 p01 = __floats2half2_rn(v.x, v.y);
        __half2 p23 = __floats2half2_rn(v.z, v.w);
        uint2 pk;
        pk.x = *(uint32_t*)&p01;
        pk.y = *(uint32_t*)&p23;
        *(uint2*)(g_a2 + (long)t * 4) = pk;
    }
}

// ---------------- fp16 mma.sync GEMM (2-stage cp.async pipeline) -------------
// C[M,256] = A[M,256]fp16 x B[256,512:(Bh|Bl)]fp16^T over virtual K=512:
// chunk c in [0,8): A k-off = (c&3)*64 ; B k-off = c*64.
// Chalf optional fp16 copy of result; attnp != nullptr fuses the
// attention-score reduction into the epilogue. Cfloat may be nullptr.
__global__ void __launch_bounds__(256) k_gemm_mma(
    const __half* __restrict__ A, const __half* __restrict__ B,
    float* __restrict__ C, __half* __restrict__ Chalf,
    const float* __restrict__ attnp, int M)
{
    extern __shared__ char sm[];
    uint32_t sbase = smem_u32(sm);
    const int tid = threadIdx.x;
    const int wid = tid >> 5, lid = tid & 31;
    const int bm = blockIdx.y * 128, bn = blockIdx.x * 128;
    const int wm = (wid >> 2) * 64, wn = (wid & 3) * 32;

    const int arow = (lid & 7) + ((lid >> 3) & 1) * 8;
    const int acol = (lid >> 4) * 8;
    const int q = lid >> 3;
    const int brow = (lid & 7) + (q >> 1) * 8;
    const int bcol = (q & 1) * 8;

    float acc[4][4][4];
#pragma unroll
    for (int mi = 0; mi < 4; mi++)
#pragma unroll
        for (int ni = 0; ni < 4; ni++)
#pragma unroll
            for (int j = 0; j < 4; j++) acc[mi][ni][j] = 0.f;

    auto load_chunk = [&](int c, int s) {
        uint32_t abase = sbase + s * 32768;
        int aoff = (c & 3) * 64;
#pragma unroll
        for (int it = 0; it < 4; it++) {
            int idx = tid + it * 256;
            int row = idx >> 3, col = (idx & 7) * 8;
            long ar = bm + row; if (ar >= M) ar = M - 1;
            cp16(abase + SWZ(row * 128 + col * 2), A + ar * 256 + aoff + col);
        }
#pragma unroll
        for (int it = 0; it < 4; it++) {
            int idx = tid + it * 256;
            int row = idx >> 3, col = (idx & 7) * 8;
            cp16(abase + 16384 + SWZ(row * 128 + col * 2),
                 B + (long)(bn + row) * KB2 + c * 64 + col);
        }
        asm volatile("cp.async.commit_group;" ::: "memory");
    };

    auto compute_chunk = [&](int s) {
        uint32_t abase = sbase + s * 32768;
        uint32_t bbase = abase + 16384;
#pragma unroll
        for (int ks = 0; ks < 4; ks++) {
            uint32_t a[4][4];
#pragma unroll
            for (int mi = 0; mi < 4; mi++)
                ldm_x4(a[mi], abase + SWZ((wm + mi * 16 + arow) * 128 +
                                          (ks * 16 + acol) * 2));
            uint32_t b[2][4];
#pragma unroll
            for (int nj = 0; nj < 2; nj++)
                ldm_x4(b[nj], bbase + SWZ((wn + nj * 16 + brow) * 128 +
                                          (ks * 16 + bcol) * 2));
#pragma unroll
            for (int mi = 0; mi < 4; mi++)
#pragma unroll
                for (int ni = 0; ni < 4; ni++)
                    mma16816(acc[mi][ni], a[mi],
                             b[ni >> 1][(ni & 1) * 2], b[ni >> 1][(ni & 1) * 2 + 1]);
        }
    };

    load_chunk(0, 0);
    const int NC = 8;
    for (int c = 0; c < NC; c++) {
        if (c + 1 < NC) {
            load_chunk(c + 1, (c + 1) & 1);
            asm volatile("cp.async.wait_group 1;" ::: "memory");
        } else {
            asm volatile("cp.async.wait_group 0;" ::: "memory");
        }
        __syncthreads();
        compute_chunk(c & 1);
        __syncthreads();
    }

    const int g = lid >> 2, tig = lid & 3;

#pragma unroll
    for (int mi = 0; mi < 4; mi++) {
        int r0 = bm + wm + mi * 16 + g;
#pragma unroll
        for (int ni = 0; ni < 4; ni++) {
            int col = bn + wn + ni * 8 + tig * 2;
#pragma unroll
            for (int h2 = 0; h2 < 2; h2++) {
                int r = r0 + h2 * 8;
                if (r < M) {
                    float c0 = acc[mi][ni][h2 * 2];
                    float c1 = acc[mi][ni][h2 * 2 + 1];
                    if (C)
                        *(float2*)(C + (long)r * 256 + col) = make_float2(c0, c1);
                    if (Chalf)
                        *(__half2*)(Chalf + (long)r * 256 + col) =
                            __floats2half2_rn(c0, c1);
                }
            }
        }
    }

    // fused attention-score reduction (GEMM1 only)
    if (attnp) {
        int hh = ((bn + wn) >> 6) & 3;
        int dbase = (bn + wn) & 63;
        float as[8], ad[8];
#pragma unroll
        for (int ni = 0; ni < 4; ni++)
#pragma unroll
            for (int c2 = 0; c2 < 2; c2++) {
                int dd = dbase + ni * 8 + tig * 2 + c2;
                as[ni * 2 + c2] = __ldg(attnp + hh * 128 + dd);
                ad[ni * 2 + c2] = __ldg(attnp + hh * 128 + 64 + dd);
            }
#pragma unroll
        for (int mi = 0; mi < 4; mi++)
#pragma unroll
            for (int h2 = 0; h2 < 2; h2++) {
                int r = bm + wm + mi * 16 + g + h2 * 8;
                if (r < M) {
                    float ps = 0.f, pd = 0.f;
#pragma unroll
                    for (int ni = 0; ni < 4; ni++) {
                        float c0 = acc[mi][ni][h2 * 2];
                        float c1 = acc[mi][ni][h2 * 2 + 1];
                        ps += c0 * as[ni * 2] + c1 * as[ni * 2 + 1];
                        pd += c0 * ad[ni * 2] + c1 * ad[ni * 2 + 1];
                    }
                    atomicAdd(&g_ssrc[r * 4 + hh], ps);
                    atomicAdd(&g_sdst[r * 4 + hh], pd);
                }
            }
    }
}

__device__ __forceinline__ float leaky(float v) {
    return v > 0.f ? v : 0.2f * v;
}

// ---------------- gather aggregation + alpha + normalize + fp16 pack --------
__global__ void __launch_bounds__(64) k_agg() {
    __shared__ int   s_src[64];
    __shared__ float s_alp[64][4];
    int d = blockIdx.x;
    int j = threadIdx.x;             // 0..63 : float4 group within 256-row
    int h = j >> 4;
    int beg = g_off[d], cnt = g_cnt[d];
    float4 sd4 = *(const float4*)(g_sdst + d * 4);
    float4 acc = make_float4(0.f, 0.f, 0.f, 0.f);
    float asum = 0.f;
    for (int base = 0; base < cnt; base += 64) {
        int nb = min(64, cnt - base);
        if (j < nb) {
            int k = beg + base + j;
            int s = g_srcs[k];
            s_src[j] = s;
            float4 sv = *(const float4*)(g_ssrc + s * 4);
            s_alp[j][0] = __expf(leaky(sv.x + sd4.x));
            s_alp[j][1] = __expf(leaky(sv.y + sd4.y));
            s_alp[j][2] = __expf(leaky(sv.z + sd4.z));
            s_alp[j][3] = __expf(leaky(sv.w + sd4.w));
        }
        __syncthreads();
#pragma unroll 4
        for (int t = 0; t < nb; t++) {
            int s = s_src[t];
            float a = s_alp[t][h];
            const __half2* hp = (const __half2*)(g_hf + (long)s * HD + j * 4);
            float2 f0 = __half22float2(hp[0]);
            float2 f1 = __half22float2(hp[1]);
            asum += a;
            acc.x = fmaf(a, f0.x, acc.x);
            acc.y = fmaf(a, f0.y, acc.y);
            acc.z = fmaf(a, f1.x, acc.z);
            acc.w = fmaf(a, f1.y, acc.w);
        }
        __syncthreads();
    }
    float inv = 1.f / (asum + 1e-8f);
    __half2 p01 = __floats2half2_rn(acc.x * inv, acc.y * inv);
    __half2 p23 = __floats2half2_rn(acc.z * inv, acc.w * inv);
    uint2 pk;
    pk.x = *(uint32_t*)&p01;
    pk.y = *(uint32_t*)&p23;
    *(uint2*)(g_o2 + (long)d * HD + j * 4) = pk;
}

// ---------------- launch ----------------------------------------------------
extern "C" void kernel_launch(void* const* d_in, const int* in_sizes, int n_in,
                              void* d_out, int out_size)
{
    const float* x    = (const float*)d_in[0];
    const int*   ei   = (const int*)  d_in[1];
    const float* W    = (const float*)d_in[2];
    const float* attn = (const float*)d_in[3];
    const float* Wout = (const float*)d_in[4];
    float*       out  = (float*)d_out;

    void *p_hf, *p_a2, *p_o2, *p_b1, *p_b2;
    cudaGetSymbolAddress(&p_hf, g_hf);
    cudaGetSymbolAddress(&p_a2, g_a2);
    cudaGetSymbolAddress(&p_o2, g_o2);
    cudaGetSymbolAddress(&p_b1, g_b1);
    cudaGetSymbolAddress(&p_b2, g_b2);

    cudaFuncSetAttribute(k_gemm_mma, cudaFuncAttributeMaxDynamicSharedMemorySize, 65536);

    // side stream for the CSR-build chain (capture-safe fork/join) — R11 layout.
    cudaStream_t s1;
    cudaStreamCreateWithFlags(&s1, cudaStreamNonBlocking);
    cudaEvent_t e0, e1;
    cudaEventCreateWithFlags(&e0, cudaEventDisableTiming);
    cudaEventCreateWithFlags(&e1, cudaEventDisableTiming);

    int eb = (Ee + 255) / 256;

    k_init0<<<(NH + 255) / 256, 256>>>();

    // fork: CSR build (hist -> offs -> edge_sort) on s1
    cudaEventRecord(e0, 0);
    cudaStreamWaitEvent(s1, e0, 0);
    k_hist<<<eb, 256, 0, s1>>>(ei);
    k_offs<<<(Nn + 255) / 256, 256, 0, s1>>>();
    k_edge_sort<<<(Ee / 4 + 255) / 256, 256, 0, s1>>>(ei);
    cudaEventRecord(e1, s1);

    // main stream: prep + GEMM1 (independent of CSR build)
    k_prep<<<256 + (Nn * 64 + 255) / 256, 256>>>(W, Wout, x);

    dim3 gg(2, (Nn + 127) / 128);           // n-tiles fast -> A shared via L2
    k_gemm_mma<<<gg, 256, 65536>>>((const __half*)p_a2,
                                   (const __half*)p_b1,
                                   (float*)nullptr, (__half*)p_hf, attn, Nn);

    // join: agg needs both GEMM1 results and the CSR permutation
    cudaStreamWaitEvent(0, e1, 0);

    k_agg<<<Nn, 64>>>();

    k_gemm_mma<<<gg, 256, 65536>>>((const __half*)p_o2,
                                   (const __half*)p_b2,
                                   out, (__half*)nullptr,
                                   (const float*)nullptr, Nn);
}

// round 14
// speedup vs baseline: 1.4026x; 1.1052x over previous
#include <cuda_runtime.h>
#include <cuda_bf16.h>
#include <cuda_fp16.h>
#include <math.h>
#include <stdint.h>

#define Nn   50000
#define Ee   1000000
#define Hh   4
#define Dd   64
#define NH   (Nn * Hh)   // 200000
#define HD   (Hh * Dd)   // 256
#define KB2  512         // B storage: [Bh | Bl] fp16; virtual GEMM K = 512

// ---------------- scratch (device globals; no allocation allowed) ----------
__device__ __half g_hf[Nn * HD];    // fp16 node features (GEMM1 out, gather in)
__device__ float  g_ssrc[NH];
__device__ float  g_sdst[NH];
// CSR (dst-bucketed) edge structures
__device__ int    g_cnt[Nn];
__device__ int    g_off[Nn];
__device__ int    g_cur[Nn];
__device__ int    g_srcs[Ee];
__device__ int    g_total;          // global offset counter
// fp16 GEMM operands
__device__ __half g_a2[Nn * HD];    // x in fp16 (GEMM1 A)
__device__ __half g_o2[Nn * HD];    // normalized out_h in fp16 (GEMM2 A)
__device__ __half g_b1[256 * KB2];  // W  head-blocked [n][Bh|Bl], row n = out col
__device__ __half g_b2[256 * KB2];  // W_out transposed [n][Bh|Bl]

#define SWZ(o) ((o) ^ (((o) >> 3) & 0x70))

__device__ __forceinline__ uint32_t smem_u32(const void* p) {
    uint32_t a;
    asm("{ .reg .u64 t; cvta.to.shared.u64 t, %1; cvt.u32.u64 %0, t; }"
        : "=r"(a) : "l"(p));
    return a;
}
__device__ __forceinline__ void cp16(uint32_t dst, const void* src) {
    asm volatile("cp.async.cg.shared.global [%0], [%1], 16;"
                 :: "r"(dst), "l"(src) : "memory");
}
__device__ __forceinline__ void ldm_x4(uint32_t* r, uint32_t addr) {
    asm volatile("ldmatrix.sync.aligned.m8n8.x4.shared.b16 {%0,%1,%2,%3}, [%4];"
                 : "=r"(r[0]), "=r"(r[1]), "=r"(r[2]), "=r"(r[3]) : "r"(addr));
}
__device__ __forceinline__ void mma16816(float* c, const uint32_t* a,
                                         uint32_t b0, uint32_t b1) {
    asm volatile(
        "mma.sync.aligned.m16n8k16.row.col.f32.f16.f16.f32 "
        "{%0,%1,%2,%3}, {%4,%5,%6,%7}, {%8,%9}, {%0,%1,%2,%3};"
        : "+f"(c[0]), "+f"(c[1]), "+f"(c[2]), "+f"(c[3])
        : "r"(a[0]), "r"(a[1]), "r"(a[2]), "r"(a[3]), "r"(b0), "r"(b1));
}

// ---------------- init + CSR build ------------------------------------------
__global__ void k_init0() {
    int i = blockIdx.x * blockDim.x + threadIdx.x;
    if (i == 0) g_total = 0;
    if (i < Nn) g_cnt[i] = 0;
    if (i < NH) { g_ssrc[i] = 0.f; g_sdst[i] = 0.f; }
}
__global__ void k_hist(const int* __restrict__ ei) {
    int e = blockIdx.x * blockDim.x + threadIdx.x;
    if (e < Ee) atomicAdd(&g_cnt[ei[Ee + e]], 1);
}
// parallel offsets: warp-scan + one global atomic per warp.
__global__ void k_offs() {
    int i = blockIdx.x * blockDim.x + threadIdx.x;
    int lane = threadIdx.x & 31;
    int c = (i < Nn) ? g_cnt[i] : 0;
    int incl = c;
#pragma unroll
    for (int o = 1; o < 32; o <<= 1) {
        int v = __shfl_up_sync(0xFFFFFFFFu, incl, o);
        if (lane >= o) incl += v;
    }
    int total = __shfl_sync(0xFFFFFFFFu, incl, 31);
    int base = 0;
    if (lane == 31) base = atomicAdd(&g_total, total);
    base = __shfl_sync(0xFFFFFFFFu, base, 31);
    int off = base + incl - c;
    if (i < Nn) { g_off[i] = off; g_cur[i] = off; }
}

// ---------------- edge pass: pure permutation build --------------------------
__global__ void k_edge_sort(const int* __restrict__ ei) {
    int t = blockIdx.x * blockDim.x + threadIdx.x;
    int e0 = t * 4;
    if (e0 >= Ee) return;
    int4 sv = *(const int4*)(ei + e0);
    int4 dv = *(const int4*)(ei + Ee + e0);
    int ss4[4] = { sv.x, sv.y, sv.z, sv.w };
    int dd4[4] = { dv.x, dv.y, dv.z, dv.w };
#pragma unroll
    for (int i = 0; i < 4; i++) {
        int pos = atomicAdd(&g_cur[dd4[i]], 1);
        g_srcs[pos] = ss4[i];
    }
}

// ---------------- merged prep: weights (blocks 0..255) + x (rest) -----------
__global__ void k_prep(const float* __restrict__ W, const float* __restrict__ Wout,
                       const float* __restrict__ x) {
    if (blockIdx.x < 256) {
        int t = blockIdx.x * 256 + threadIdx.x;   // 65536
        int n = t >> 8, k = t & 255;
        float v1 = W[(((n >> 6) * 256) + k) * 64 + (n & 63)];
        __half h1 = __float2half_rn(v1);
        __half l1 = __float2half_rn(v1 - __half2float(h1));
        g_b1[n * KB2 + k]       = h1;
        g_b1[n * KB2 + 256 + k] = l1;
        float v2 = Wout[k * 256 + n];
        __half h2 = __float2half_rn(v2);
        __half l2 = __float2half_rn(v2 - __half2float(h2));
        g_b2[n * KB2 + k]       = h2;
        g_b2[n * KB2 + 256 + k] = l2;
    } else {
        int t = (blockIdx.x - 256) * 256 + threadIdx.x;   // per float4
        if (t >= Nn * 64) return;
        float4 v = ((const float4*)x)[t];
        __half2 p01 = __floats2half2_rn(v.x, v.y);
        __half2 p23 = __floats2half2_rn(v.z, v.w);
        uint2 pk;
        pk.x = *(uint32_t*)&p01;
        pk.y = *(uint32_t*)&p23;
        *(uint2*)(g_a2 + (long)t * 4) = pk;
    }
}

// ---------------- fp16 mma.sync GEMM (2-stage cp.async pipeline) -------------
__global__ void __launch_bounds__(256) k_gemm_mma(
    const __half* __restrict__ A, const __half* __restrict__ B,
    float* __restrict__ C, __half* __restrict__ Chalf,
    const float* __restrict__ attnp, int M)
{
    extern __shared__ char sm[];
    uint32_t sbase = smem_u32(sm);
    const int tid = threadIdx.x;
    const int wid = tid >> 5, lid = tid & 31;
    const int bm = blockIdx.y * 128, bn = blockIdx.x * 128;
    const int wm = (wid >> 2) * 64, wn = (wid & 3) * 32;

    const int arow = (lid & 7) + ((lid >> 3) & 1) * 8;
    const int acol = (lid >> 4) * 8;
    const int q = lid >> 3;
    const int brow = (lid & 7) + (q >> 1) * 8;
    const int bcol = (q & 1) * 8;

    float acc[4][4][4];
#pragma unroll
    for (int mi = 0; mi < 4; mi++)
#pragma unroll
        for (int ni = 0; ni < 4; ni++)
#pragma unroll
            for (int j = 0; j < 4; j++) acc[mi][ni][j] = 0.f;

    auto load_chunk = [&](int c, int s) {
        uint32_t abase = sbase + s * 32768;
        int aoff = (c & 3) * 64;
#pragma unroll
        for (int it = 0; it < 4; it++) {
            int idx = tid + it * 256;
            int row = idx >> 3, col = (idx & 7) * 8;
            long ar = bm + row; if (ar >= M) ar = M - 1;
            cp16(abase + SWZ(row * 128 + col * 2), A + ar * 256 + aoff + col);
        }
#pragma unroll
        for (int it = 0; it < 4; it++) {
            int idx = tid + it * 256;
            int row = idx >> 3, col = (idx & 7) * 8;
            cp16(abase + 16384 + SWZ(row * 128 + col * 2),
                 B + (long)(bn + row) * KB2 + c * 64 + col);
        }
        asm volatile("cp.async.commit_group;" ::: "memory");
    };

    auto compute_chunk = [&](int s) {
        uint32_t abase = sbase + s * 32768;
        uint32_t bbase = abase + 16384;
#pragma unroll
        for (int ks = 0; ks < 4; ks++) {
            uint32_t a[4][4];
#pragma unroll
            for (int mi = 0; mi < 4; mi++)
                ldm_x4(a[mi], abase + SWZ((wm + mi * 16 + arow) * 128 +
                                          (ks * 16 + acol) * 2));
            uint32_t b[2][4];
#pragma unroll
            for (int nj = 0; nj < 2; nj++)
                ldm_x4(b[nj], bbase + SWZ((wn + nj * 16 + brow) * 128 +
                                          (ks * 16 + bcol) * 2));
#pragma unroll
            for (int mi = 0; mi < 4; mi++)
#pragma unroll
                for (int ni = 0; ni < 4; ni++)
                    mma16816(acc[mi][ni], a[mi],
                             b[ni >> 1][(ni & 1) * 2], b[ni >> 1][(ni & 1) * 2 + 1]);
        }
    };

    load_chunk(0, 0);
    const int NC = 8;
    for (int c = 0; c < NC; c++) {
        if (c + 1 < NC) {
            load_chunk(c + 1, (c + 1) & 1);
            asm volatile("cp.async.wait_group 1;" ::: "memory");
        } else {
            asm volatile("cp.async.wait_group 0;" ::: "memory");
        }
        __syncthreads();
        compute_chunk(c & 1);
        __syncthreads();
    }

    const int g = lid >> 2, tig = lid & 3;

#pragma unroll
    for (int mi = 0; mi < 4; mi++) {
        int r0 = bm + wm + mi * 16 + g;
#pragma unroll
        for (int ni = 0; ni < 4; ni++) {
            int col = bn + wn + ni * 8 + tig * 2;
#pragma unroll
            for (int h2 = 0; h2 < 2; h2++) {
                int r = r0 + h2 * 8;
                if (r < M) {
                    float c0 = acc[mi][ni][h2 * 2];
                    float c1 = acc[mi][ni][h2 * 2 + 1];
                    if (C)
                        *(float2*)(C + (long)r * 256 + col) = make_float2(c0, c1);
                    if (Chalf)
                        *(__half2*)(Chalf + (long)r * 256 + col) =
                            __floats2half2_rn(c0, c1);
                }
            }
        }
    }

    // fused attention-score reduction (GEMM1 only)
    if (attnp) {
        int hh = ((bn + wn) >> 6) & 3;
        int dbase = (bn + wn) & 63;
        float as[8], ad[8];
#pragma unroll
        for (int ni = 0; ni < 4; ni++)
#pragma unroll
            for (int c2 = 0; c2 < 2; c2++) {
                int dd = dbase + ni * 8 + tig * 2 + c2;
                as[ni * 2 + c2] = __ldg(attnp + hh * 128 + dd);
                ad[ni * 2 + c2] = __ldg(attnp + hh * 128 + 64 + dd);
            }
#pragma unroll
        for (int mi = 0; mi < 4; mi++)
#pragma unroll
            for (int h2 = 0; h2 < 2; h2++) {
                int r = bm + wm + mi * 16 + g + h2 * 8;
                if (r < M) {
                    float ps = 0.f, pd = 0.f;
#pragma unroll
                    for (int ni = 0; ni < 4; ni++) {
                        float c0 = acc[mi][ni][h2 * 2];
                        float c1 = acc[mi][ni][h2 * 2 + 1];
                        ps += c0 * as[ni * 2] + c1 * as[ni * 2 + 1];
                        pd += c0 * ad[ni * 2] + c1 * ad[ni * 2 + 1];
                    }
                    atomicAdd(&g_ssrc[r * 4 + hh], ps);
                    atomicAdd(&g_sdst[r * 4 + hh], pd);
                }
            }
    }
}

__device__ __forceinline__ float leaky(float v) {
    return v > 0.f ? v : 0.2f * v;
}

// ---------------- gather aggregation: one WARP per dst node ------------------
// Lane l owns 8 halves (16 B) of the 512 B row -> one LDG.128 per edge.
// Per-warp smem staging, __syncwarp only: warps progress independently.
__global__ void __launch_bounds__(256) k_agg() {
    __shared__ int   s_src[8][32];
    __shared__ float s_alp[8][32][4];
    int warp = threadIdx.x >> 5;
    int lane = threadIdx.x & 31;
    int d = blockIdx.x * 8 + warp;
    if (d >= Nn) return;
    int beg = g_off[d], cnt = g_cnt[d];
    float4 sd4 = *(const float4*)(g_sdst + d * 4);
    int h = lane >> 3;               // head for this lane's 8-half segment
    float acc[8];
#pragma unroll
    for (int i = 0; i < 8; i++) acc[i] = 0.f;
    float asum = 0.f;

    for (int base = 0; base < cnt; base += 32) {
        int nb = min(32, cnt - base);
        if (lane < nb) {
            int k = beg + base + lane;
            int s = g_srcs[k];
            s_src[warp][lane] = s;
            float4 sv = *(const float4*)(g_ssrc + s * 4);
            s_alp[warp][lane][0] = __expf(leaky(sv.x + sd4.x));
            s_alp[warp][lane][1] = __expf(leaky(sv.y + sd4.y));
            s_alp[warp][lane][2] = __expf(leaky(sv.z + sd4.z));
            s_alp[warp][lane][3] = __expf(leaky(sv.w + sd4.w));
        }
        __syncwarp();
#pragma unroll 8
        for (int t = 0; t < nb; t++) {
            int s = s_src[warp][t];
            float a = s_alp[warp][t][h];
            uint4 v = *(const uint4*)(g_hf + (long)s * HD + lane * 8);
            __half2 q0 = *(__half2*)&v.x;
            __half2 q1 = *(__half2*)&v.y;
            __half2 q2 = *(__half2*)&v.z;
            __half2 q3 = *(__half2*)&v.w;
            float2 f0 = __half22float2(q0);
            float2 f1 = __half22float2(q1);
            float2 f2 = __half22float2(q2);
            float2 f3 = __half22float2(q3);
            asum += a;
            acc[0] = fmaf(a, f0.x, acc[0]);
            acc[1] = fmaf(a, f0.y, acc[1]);
            acc[2] = fmaf(a, f1.x, acc[2]);
            acc[3] = fmaf(a, f1.y, acc[3]);
            acc[4] = fmaf(a, f2.x, acc[4]);
            acc[5] = fmaf(a, f2.y, acc[5]);
            acc[6] = fmaf(a, f3.x, acc[6]);
            acc[7] = fmaf(a, f3.y, acc[7]);
        }
        __syncwarp();
    }

    float inv = 1.f / (asum + 1e-8f);
    __half2 p0 = __floats2half2_rn(acc[0] * inv, acc[1] * inv);
    __half2 p1 = __floats2half2_rn(acc[2] * inv, acc[3] * inv);
    __half2 p2 = __floats2half2_rn(acc[4] * inv, acc[5] * inv);
    __half2 p3 = __floats2half2_rn(acc[6] * inv, acc[7] * inv);
    uint4 pk;
    pk.x = *(uint32_t*)&p0;
    pk.y = *(uint32_t*)&p1;
    pk.z = *(uint32_t*)&p2;
    pk.w = *(uint32_t*)&p3;
    *(uint4*)(g_o2 + (long)d * HD + lane * 8) = pk;
}

// ---------------- launch ----------------------------------------------------
extern "C" void kernel_launch(void* const* d_in, const int* in_sizes, int n_in,
                              void* d_out, int out_size)
{
    const float* x    = (const float*)d_in[0];
    const int*   ei   = (const int*)  d_in[1];
    const float* W    = (const float*)d_in[2];
    const float* attn = (const float*)d_in[3];
    const float* Wout = (const float*)d_in[4];
    float*       out  = (float*)d_out;

    void *p_hf, *p_a2, *p_o2, *p_b1, *p_b2;
    cudaGetSymbolAddress(&p_hf, g_hf);
    cudaGetSymbolAddress(&p_a2, g_a2);
    cudaGetSymbolAddress(&p_o2, g_o2);
    cudaGetSymbolAddress(&p_b1, g_b1);
    cudaGetSymbolAddress(&p_b2, g_b2);

    cudaFuncSetAttribute(k_gemm_mma, cudaFuncAttributeMaxDynamicSharedMemorySize, 65536);

    // side stream for the CSR-build chain (capture-safe fork/join).
    cudaStream_t s1;
    cudaStreamCreateWithFlags(&s1, cudaStreamNonBlocking);
    cudaEvent_t e0, e1;
    cudaEventCreateWithFlags(&e0, cudaEventDisableTiming);
    cudaEventCreateWithFlags(&e1, cudaEventDisableTiming);

    int eb = (Ee + 255) / 256;

    k_init0<<<(NH + 255) / 256, 256>>>();

    // fork: CSR build (hist -> offs -> edge_sort) on s1
    cudaEventRecord(e0, 0);
    cudaStreamWaitEvent(s1, e0, 0);
    k_hist<<<eb, 256, 0, s1>>>(ei);
    k_offs<<<(Nn + 255) / 256, 256, 0, s1>>>();
    k_edge_sort<<<(Ee / 4 + 255) / 256, 256, 0, s1>>>(ei);
    cudaEventRecord(e1, s1);

    // main stream: prep + GEMM1 (independent of CSR build)
    k_prep<<<256 + (Nn * 64 + 255) / 256, 256>>>(W, Wout, x);

    dim3 gg(2, (Nn + 127) / 128);           // n-tiles fast -> A shared via L2
    k_gemm_mma<<<gg, 256, 65536>>>((const __half*)p_a2,
                                   (const __half*)p_b1,
                                   (float*)nullptr, (__half*)p_hf, attn, Nn);

    // join: agg needs both GEMM1 results and the CSR permutation
    cudaStreamWaitEvent(0, e1, 0);

    k_agg<<<(Nn + 7) / 8, 256>>>();

    k_gemm_mma<<<gg, 256, 65536>>>((const __half*)p_o2,
                                   (const __half*)p_b2,
                                   out, (__half*)nullptr,
                                   (const float*)nullptr, Nn);
}